// round 4
// baseline (speedup 1.0000x reference)
#include <cuda_runtime.h>
#include <cstdint>

// Problem constants
#define B_DIM   4096
#define F_DIM   32
#define C_DIM   128
#define K1      32
#define K2      496
#define K3      4960
#define K_TOT   5488            // 32 + 496 + 4960
#define KPAD    5632            // padded to SPLITK * NCHUNK * KC
#define SPLITK  8
#define KPS     (KPAD / SPLITK) // 704 k's per split
#define KC      32              // k-chunk
#define NCHUNK  (KPS / KC)      // 22
#define MT      64
#define NT      64

// Scratch (static __device__ — no allocations allowed)
__device__ float g_Wcat[KPAD * C_DIM];                       // ~2.9 MB
__device__ int   g_packed[KPAD];                             // packed (i | j<<6 | k<<12), sentinel = 32
__device__ float g_partial[(size_t)SPLITK * B_DIM * C_DIM];  // 16 MB

// ---------------------------------------------------------------------------
// Prep 1: pack combo indices. Sentinel index 32 maps to the smem 1.0f slot.
// ---------------------------------------------------------------------------
__global__ void pack_kernel(const int* __restrict__ idx1,
                            const int* __restrict__ idx2,
                            const int* __restrict__ idx3) {
    int k = blockIdx.x * blockDim.x + threadIdx.x;
    if (k >= KPAD) return;
    int a = 32, b = 32, c = 32;
    if (k < K1) {
        a = idx1[k];
    } else if (k < K1 + K2) {
        int j = k - K1;
        a = idx2[2 * j];
        b = idx2[2 * j + 1];
    } else if (k < K_TOT) {
        int j = k - (K1 + K2);
        a = idx3[3 * j];
        b = idx3[3 * j + 1];
        c = idx3[3 * j + 2];
    }
    g_packed[k] = a | (b << 6) | (c << 12);
}

// ---------------------------------------------------------------------------
// Prep 2: concatenate W1/W2/W3 into g_Wcat (pad rows = 0 -> contribute nothing)
// ---------------------------------------------------------------------------
__global__ void wcat_kernel(const float* __restrict__ W1,
                            const float* __restrict__ W2,
                            const float* __restrict__ W3) {
    int e = blockIdx.x * blockDim.x + threadIdx.x;   // element over KPAD*128
    if (e >= KPAD * C_DIM) return;
    int k = e >> 7;
    float v = 0.0f;
    if (k < K1)               v = W1[e];
    else if (k < K1 + K2)     v = W2[e - K1 * C_DIM];
    else if (k < K_TOT)       v = W3[e - (K1 + K2) * C_DIM];
    g_Wcat[e] = v;
}

// ---------------------------------------------------------------------------
// Main: split-K GEMM with on-the-fly product generation.
// Block: 64 threads, computes MT x NT tile of a K-split partial.
// Each thread: 8x8 register tile. grid = (C/NT, B/MT, SPLITK)
// ---------------------------------------------------------------------------
__global__ void __launch_bounds__(64) main_kernel(const float* __restrict__ x) {
    __shared__ float xs[MT][F_DIM + 2];    // stride 34 keeps (t*34+i)%32 distinct-ish; col 32 = 1.0f
    __shared__ float sP[KC][MT];           // products, [k][m]
    __shared__ float sW[KC][NT];           // weights,  [k][n]
    __shared__ int   sIdx[KC];

    const int t  = threadIdx.x;            // 0..63
    const int n0 = blockIdx.x * NT;
    const int m0 = blockIdx.y * MT;
    const int s  = blockIdx.z;
    const int k0base = s * KPS;

    // Load this block's x rows: thread t owns row m0+t (32 floats = 8 float4)
    {
        const float4* xrow = (const float4*)(x + (size_t)(m0 + t) * F_DIM);
        #pragma unroll
        for (int i = 0; i < 8; i++) {
            float4 v = xrow[i];
            xs[t][i * 4 + 0] = v.x;
            xs[t][i * 4 + 1] = v.y;
            xs[t][i * 4 + 2] = v.z;
            xs[t][i * 4 + 3] = v.w;
        }
        xs[t][32] = 1.0f;   // sentinel: missing factor multiplies by 1
    }

    float acc[8][8];
    #pragma unroll
    for (int i = 0; i < 8; i++)
        #pragma unroll
        for (int j = 0; j < 8; j++) acc[i][j] = 0.0f;

    const int ty = t >> 3;   // 0..7 -> m sub-tile
    const int tx = t & 7;    // 0..7 -> n sub-tile

    for (int ch = 0; ch < NCHUNK; ch++) {
        const int k0 = k0base + ch * KC;

        __syncthreads();   // protect sP/sW from previous-iteration readers

        // Stage packed indices (warp 0 lanes 0..31)
        if (t < KC) sIdx[t] = g_packed[k0 + t];

        // Stage W chunk [KC][NT] = 2048 floats = 512 float4, 8 per thread
        {
            const float* Wbase = g_Wcat + (size_t)k0 * C_DIM + n0;
            #pragma unroll
            for (int i = 0; i < 8; i++) {
                int f  = t + 64 * i;        // float4 index 0..511
                int kk = f >> 4;            // row 0..31
                int c4 = f & 15;            // float4 within row
                float4 w = *(const float4*)(Wbase + (size_t)kk * C_DIM + c4 * 4);
                *(float4*)(&sW[kk][c4 * 4]) = w;
            }
        }

        __syncthreads();   // sIdx + sW visible

        // Compute products for row m = t, all KC combos (branch-free via sentinel)
        #pragma unroll
        for (int kk = 0; kk < KC; kk++) {
            int p = sIdx[kk];
            float v = xs[t][p & 63] * xs[t][(p >> 6) & 63] * xs[t][(p >> 12) & 63];
            sP[kk][t] = v;
        }

        __syncthreads();   // sP visible

        // 8x8 register GEMM over the chunk
        #pragma unroll 8
        for (int kk = 0; kk < KC; kk++) {
            float a[8], b[8];
            *(float4*)(a)     = *(const float4*)(&sP[kk][ty * 8]);
            *(float4*)(a + 4) = *(const float4*)(&sP[kk][ty * 8 + 4]);
            *(float4*)(b)     = *(const float4*)(&sW[kk][tx * 8]);
            *(float4*)(b + 4) = *(const float4*)(&sW[kk][tx * 8 + 4]);
            #pragma unroll
            for (int i = 0; i < 8; i++)
                #pragma unroll
                for (int j = 0; j < 8; j++)
                    acc[i][j] += a[i] * b[j];
        }
    }

    // Write partial tile: partial[s][m0+ty*8+i][n0+tx*8+j]
    float* pout = g_partial + ((size_t)s * B_DIM + m0) * C_DIM + n0;
    #pragma unroll
    for (int i = 0; i < 8; i++) {
        float* row = pout + (size_t)(ty * 8 + i) * C_DIM + tx * 8;
        *(float4*)(row)     = make_float4(acc[i][0], acc[i][1], acc[i][2], acc[i][3]);
        *(float4*)(row + 4) = make_float4(acc[i][4], acc[i][5], acc[i][6], acc[i][7]);
    }
}

// ---------------------------------------------------------------------------
// Reduce: out = bias + sum_s partial[s]   (float4-vectorized)
// ---------------------------------------------------------------------------
__global__ void reduce_kernel(const float* __restrict__ bias,
                              float* __restrict__ out) {
    int i = blockIdx.x * blockDim.x + threadIdx.x;     // float4 index, 131072 total
    if (i >= (B_DIM * C_DIM) / 4) return;
    const float4* bias4 = (const float4*)bias;
    float4 accv = bias4[i & 31];                       // c4 = i % (128/4)
    const float4* p4 = (const float4*)g_partial;
    #pragma unroll
    for (int s = 0; s < SPLITK; s++) {
        float4 v = p4[(size_t)s * (B_DIM * C_DIM / 4) + i];
        accv.x += v.x; accv.y += v.y; accv.z += v.z; accv.w += v.w;
    }
    ((float4*)out)[i] = accv;
}

// ---------------------------------------------------------------------------
// Launch
// ---------------------------------------------------------------------------
extern "C" void kernel_launch(void* const* d_in, const int* in_sizes, int n_in,
                              void* d_out, int out_size) {
    const float* x    = (const float*)d_in[0];
    const float* bias = (const float*)d_in[1];
    const float* W1   = (const float*)d_in[2];
    const float* W2   = (const float*)d_in[3];
    const float* W3   = (const float*)d_in[4];
    const int*   idx1 = (const int*)d_in[5];
    const int*   idx2 = (const int*)d_in[6];
    const int*   idx3 = (const int*)d_in[7];
    float* out = (float*)d_out;

    pack_kernel<<<(KPAD + 127) / 128, 128>>>(idx1, idx2, idx3);
    wcat_kernel<<<(KPAD * C_DIM + 255) / 256, 256>>>(W1, W2, W3);

    dim3 grid(C_DIM / NT, B_DIM / MT, SPLITK);   // (2, 64, 8) = 1024 blocks
    main_kernel<<<grid, 64>>>(x);

    reduce_kernel<<<(B_DIM * C_DIM / 4 + 127) / 128, 128>>>(bias, out);
}

// round 7
// speedup vs baseline: 1.2188x; 1.2188x over previous
#include <cuda_runtime.h>
#include <cstdint>

// Problem constants
#define B_DIM   4096
#define F_DIM   32
#define C_DIM   128
#define K1      32
#define K2      496
#define K3      4960
#define K_TOT   5488
#define SPLITK  9
#define KC      32
#define NCH     20
#define KPS     (KC * NCH)        // 640 k's per split
#define KPAD    (SPLITK * KPS)    // 5760 (pad rows have zero W -> no contribution)
#define MT      128

// Scratch (static __device__ — no allocations allowed)
__device__ float g_Wcat[KPAD * C_DIM];                       // ~2.95 MB
__device__ int   g_packed[KPAD];                             // (i | j<<6 | k<<12), sentinel=32
__device__ float g_partial[(size_t)SPLITK * B_DIM * C_DIM];  // ~18.9 MB

// Dynamic smem layout (floats)
#define XS_FLOATS   (MT * 33)                    // stride 33: conflict-free + 1.0 slot at col 32
#define SP_FLOATS   (KC * MT)                    // 4096
#define SW_FLOATS   (2 * KC * C_DIM)             // 8192 (double buffer, 4096 floats each)
#define OFF_SP      (XS_FLOATS)
#define OFF_SW      (OFF_SP + SP_FLOATS)
#define OFF_IDX     (OFF_SW + SW_FLOATS)
#define SMEM_FLOATS (OFF_IDX + KPS)
#define SMEM_BYTES  (SMEM_FLOATS * 4)            // 68608

// ---------------------------------------------------------------------------
// Prep 1: pack combo indices. Sentinel 32 -> xs[.][32] == 1.0f
// ---------------------------------------------------------------------------
__global__ void pack_kernel(const int* __restrict__ idx1,
                            const int* __restrict__ idx2,
                            const int* __restrict__ idx3) {
    int k = blockIdx.x * blockDim.x + threadIdx.x;
    if (k >= KPAD) return;
    int a = 32, b = 32, c = 32;
    if (k < K1) {
        a = idx1[k];
    } else if (k < K1 + K2) {
        int j = k - K1;
        a = idx2[2 * j]; b = idx2[2 * j + 1];
    } else if (k < K_TOT) {
        int j = k - (K1 + K2);
        a = idx3[3 * j]; b = idx3[3 * j + 1]; c = idx3[3 * j + 2];
    }
    g_packed[k] = a | (b << 6) | (c << 12);
}

// ---------------------------------------------------------------------------
// Prep 2: concatenate W1/W2/W3 (pad rows zero)
// ---------------------------------------------------------------------------
__global__ void wcat_kernel(const float* __restrict__ W1,
                            const float* __restrict__ W2,
                            const float* __restrict__ W3) {
    int e = blockIdx.x * blockDim.x + threadIdx.x;
    if (e >= KPAD * C_DIM) return;
    int k = e >> 7;
    float v = 0.0f;
    if (k < K1)           v = W1[e];
    else if (k < K1 + K2) v = W2[e - K1 * C_DIM];
    else if (k < K_TOT)   v = W3[e - (K1 + K2) * C_DIM];
    g_Wcat[e] = v;
}

// ---------------------------------------------------------------------------
// cp.async helper
// ---------------------------------------------------------------------------
__device__ __forceinline__ void cp_async16(float* smem_dst, const float* gmem_src) {
    uint32_t s = (uint32_t)__cvta_generic_to_shared(smem_dst);
    asm volatile("cp.async.cg.shared.global [%0], [%1], 16;\n" :: "r"(s), "l"(gmem_src));
}

// Stage one full W chunk (KC*C_DIM = 4096 floats = 1024 float4) with 256 threads:
// 4 float4 per thread.
__device__ __forceinline__ void stage_w_chunk(float* dst, const float* src, int t) {
    #pragma unroll
    for (int i = 0; i < 4; i++) {
        int f4 = t + 256 * i;                 // 0..1023
        cp_async16(dst + f4 * 4, src + f4 * 4);
    }
}

// ---------------------------------------------------------------------------
// Main: split-K GEMM, on-the-fly products, fp32x2 packed FMA (FFMA2).
// Block 256 threads: MT=128 x NT=128 tile, 8x8 per thread, grid = (32, SPLITK)
// ---------------------------------------------------------------------------
__global__ void __launch_bounds__(256, 2) main_kernel(const float* __restrict__ x) {
    extern __shared__ float smem[];
    float (*xs)[33] = (float (*)[33])smem;
    float (*sP)[MT] = (float (*)[MT])(smem + OFF_SP);
    float* sW       = smem + OFF_SW;          // two buffers of KC*C_DIM floats
    int*   sIdx     = (int*)(smem + OFF_IDX);

    const int t      = threadIdx.x;
    const int m0     = blockIdx.x * MT;
    const int s      = blockIdx.y;
    const int k0base = s * KPS;

    // Fill xs: thread pair (t, t+128) loads half a row each
    {
        int r = t & 127, h = t >> 7;
        const float4* xrow = (const float4*)(x + (size_t)(m0 + r) * F_DIM);
        #pragma unroll
        for (int i = 0; i < 4; i++) {
            float4 v = xrow[h * 4 + i];
            int c = (h * 4 + i) * 4;
            xs[r][c] = v.x; xs[r][c + 1] = v.y; xs[r][c + 2] = v.z; xs[r][c + 3] = v.w;
        }
        if (h == 0) xs[r][32] = 1.0f;   // sentinel factor
    }
    // Stage all packed indices for this split once
    for (int i = t; i < KPS; i += 256) sIdx[i] = g_packed[k0base + i];

    // Prologue: async-load W chunk 0 into buffer 0 (FULL 4096 floats)
    stage_w_chunk(sW, g_Wcat + (size_t)k0base * C_DIM, t);
    asm volatile("cp.async.commit_group;\n");

    unsigned long long acc[8][4];
    #pragma unroll
    for (int i = 0; i < 8; i++)
        #pragma unroll
        for (int j = 0; j < 4; j++) acc[i][j] = 0ull;   // (0.0f, 0.0f)

    const int ty8 = (t >> 4) * 8;     // m offset
    const int tx8 = (t & 15) * 8;     // n offset
    const int pr  = t & 127;          // product row
    const int hq  = (t >> 7) * 16;    // product k-half

    for (int ch = 0; ch < NCH; ch++) {
        __syncthreads();   // xs/sIdx ready (iter 0); prior GEMM done reading sP & old sW buffer

        // Products for this chunk: branch-free 3-way product via sentinel
        #pragma unroll
        for (int q = 0; q < 16; q++) {
            int kk = hq + q;
            int p  = sIdx[ch * KC + kk];
            sP[kk][pr] = xs[pr][p & 63] * xs[pr][(p >> 6) & 63] * xs[pr][(p >> 12) & 63];
        }

        // Prefetch next W chunk into the other buffer (FULL chunk)
        if (ch + 1 < NCH) {
            stage_w_chunk(sW + ((ch + 1) & 1) * (KC * C_DIM),
                          g_Wcat + (size_t)(k0base + (ch + 1) * KC) * C_DIM, t);
        }
        asm volatile("cp.async.commit_group;\n");
        asm volatile("cp.async.wait_group 1;\n");   // current chunk's W has landed
        __syncthreads();                            // sP visible + joint W wait

        const float* Wb = sW + (ch & 1) * (KC * C_DIM);
        #pragma unroll 4
        for (int kk = 0; kk < KC; kk++) {
            float4 av0 = *(const float4*)(&sP[kk][ty8]);
            float4 av1 = *(const float4*)(&sP[kk][ty8 + 4]);
            const float* wr = Wb + kk * C_DIM + tx8;
            ulonglong2 bv0 = *(const ulonglong2*)(wr);      // pairs (b0,b1),(b2,b3)
            ulonglong2 bv1 = *(const ulonglong2*)(wr + 4);  // pairs (b4,b5),(b6,b7)
            float a_[8] = {av0.x, av0.y, av0.z, av0.w, av1.x, av1.y, av1.z, av1.w};
            unsigned long long b_[4] = {bv0.x, bv0.y, bv1.x, bv1.y};
            #pragma unroll
            for (int i = 0; i < 8; i++) {
                unsigned long long ap;
                asm("mov.b64 %0, {%1, %1};" : "=l"(ap) : "f"(a_[i]));
                #pragma unroll
                for (int j = 0; j < 4; j++)
                    asm("fma.rn.f32x2 %0, %1, %2, %0;" : "+l"(acc[i][j]) : "l"(ap), "l"(b_[j]));
            }
        }
    }

    // Write partial tile
    float* pout = g_partial + ((size_t)s * B_DIM + m0 + ty8) * C_DIM + tx8;
    #pragma unroll
    for (int i = 0; i < 8; i++) {
        ulonglong2* row = (ulonglong2*)(pout + (size_t)i * C_DIM);
        ulonglong2 v0; v0.x = acc[i][0]; v0.y = acc[i][1];
        ulonglong2 v1; v1.x = acc[i][2]; v1.y = acc[i][3];
        row[0] = v0; row[1] = v1;
    }
}

// ---------------------------------------------------------------------------
// Reduce: out = bias + sum_s partial[s]
// ---------------------------------------------------------------------------
__global__ void reduce_kernel(const float* __restrict__ bias,
                              float* __restrict__ out) {
    int i = blockIdx.x * blockDim.x + threadIdx.x;     // float4 index
    if (i >= (B_DIM * C_DIM) / 4) return;
    float4 accv = ((const float4*)bias)[i & 31];
    const float4* p4 = (const float4*)g_partial;
    #pragma unroll
    for (int s = 0; s < SPLITK; s++) {
        float4 v = p4[(size_t)s * (B_DIM * C_DIM / 4) + i];
        accv.x += v.x; accv.y += v.y; accv.z += v.z; accv.w += v.w;
    }
    ((float4*)out)[i] = accv;
}

// ---------------------------------------------------------------------------
// Launch
// ---------------------------------------------------------------------------
extern "C" void kernel_launch(void* const* d_in, const int* in_sizes, int n_in,
                              void* d_out, int out_size) {
    const float* x    = (const float*)d_in[0];
    const float* bias = (const float*)d_in[1];
    const float* W1   = (const float*)d_in[2];
    const float* W2   = (const float*)d_in[3];
    const float* W3   = (const float*)d_in[4];
    const int*   idx1 = (const int*)d_in[5];
    const int*   idx2 = (const int*)d_in[6];
    const int*   idx3 = (const int*)d_in[7];
    float* out = (float*)d_out;

    // Idempotent, capture-safe, no allocation
    cudaFuncSetAttribute(main_kernel, cudaFuncAttributeMaxDynamicSharedMemorySize, SMEM_BYTES);

    pack_kernel<<<(KPAD + 127) / 128, 128>>>(idx1, idx2, idx3);
    wcat_kernel<<<(KPAD * C_DIM + 255) / 256, 256>>>(W1, W2, W3);

    dim3 grid(B_DIM / MT, SPLITK);   // (32, 9) = 288 blocks
    main_kernel<<<grid, 256, SMEM_BYTES>>>(x);

    reduce_kernel<<<(B_DIM * C_DIM / 4 + 255) / 256, 256>>>(bias, out);
}

// round 12
// speedup vs baseline: 1.6267x; 1.3347x over previous
#include <cuda_runtime.h>
#include <cuda_bf16.h>
#include <cstdint>

// Problem constants
#define B_DIM    4096
#define F_DIM    32
#define C_DIM    128
#define K_TOT    5488
#define SPLITK   4
#define BK_SPL   1372            // real base-k per split (4*1372 = 5488)
#define BK_PAD   1376            // padded: 86 chunks * 16
#define CH_BK    16              // base-k per chunk
#define CHUNKS   86
#define KP       64              // k' columns per chunk (4 per base-k)
#define MT       128

// Scratch (static __device__ — no allocations allowed)
__device__ int   g_packed[SPLITK * BK_PAD];                       // sentinel=32
__device__ uint4 g_Bsw[SPLITK * CHUNKS * 1024];                   // pre-swizzled 16KB B chunks (~5.6MB)
__device__ float g_partial[(size_t)SPLITK * B_DIM * C_DIM];       // 8.4 MB

// Dynamic smem layout (bytes)
#define OFF_XS    0                       // 128*33*4 = 16896
#define OFF_IDX   16896                   // 1376*4   = 5504
#define OFF_SA    22528                   // 16384 (single buffer)
#define OFF_SB    38912                   // 2 x 16384 (double buffer)
#define SMEM_BYTES 71680

// swizzle within a 16KB tile of 128-byte rows: XOR chunk-col with row%8
__device__ __forceinline__ uint32_t swz(uint32_t b) { return b ^ ((b >> 3) & 0x70); }

__device__ __forceinline__ uint32_t smem_u32(const void* p) {
    uint32_t a;
    asm("{ .reg .u64 t; cvta.to.shared.u64 t, %1; cvt.u32.u64 %0, t; }" : "=r"(a) : "l"(p));
    return a;
}
__device__ __forceinline__ void cp_async16(uint32_t smem_dst, const void* gmem_src) {
    asm volatile("cp.async.cg.shared.global [%0], [%1], 16;\n" :: "r"(smem_dst), "l"(gmem_src));
}

// ---------------------------------------------------------------------------
// Prep 1: pack combo indices per split (sentinel 32 -> xs[.][32]=1)
// ---------------------------------------------------------------------------
__global__ void pack_kernel(const int* __restrict__ idx1,
                            const int* __restrict__ idx2,
                            const int* __restrict__ idx3) {
    int i = blockIdx.x * blockDim.x + threadIdx.x;
    if (i >= SPLITK * BK_PAD) return;
    int s = i / BK_PAD, bq = i - s * BK_PAD;
    int a = 32, b = 32, c = 32;
    if (bq < BK_SPL) {
        int k = s * BK_SPL + bq;
        if (k < 32) {
            a = idx1[k];
        } else if (k < 528) {
            int j = k - 32; a = idx2[2 * j]; b = idx2[2 * j + 1];
        } else {
            int j = k - 528; a = idx3[3 * j]; b = idx3[3 * j + 1]; c = idx3[3 * j + 2];
        }
    }
    g_packed[i] = a | (b << 6) | (c << 12);
}

// ---------------------------------------------------------------------------
// Prep 2: pre-swizzled bf16 B chunks, layout [n=128 rows][k'=64 cols bf16].
// Per base-k cols {4b..4b+3}: {whi, whi, wlo, wlo}.
// ---------------------------------------------------------------------------
__global__ void wq_kernel(const float* __restrict__ W1,
                          const float* __restrict__ W2,
                          const float* __restrict__ W3) {
    int e = blockIdx.x * blockDim.x + threadIdx.x;
    if (e >= SPLITK * BK_PAD * C_DIM) return;
    int n  = e & 127;
    int sb = e >> 7;
    int s  = sb / BK_PAD, bq = sb - s * BK_PAD;

    float w = 0.0f;
    if (bq < BK_SPL) {
        int k = s * BK_SPL + bq;
        if (k < 32)       w = W1[k * C_DIM + n];
        else if (k < 528) w = W2[(k - 32) * C_DIM + n];
        else              w = W3[(k - 528) * C_DIM + n];
    }
    float whi_f = __bfloat162float(__float2bfloat16(w));
    float wlo_f = w - whi_f;
    uint32_t w0, w1;
    asm("cvt.rn.bf16x2.f32 %0, %1, %1;" : "=r"(w0) : "f"(w));      // {whi, whi}
    asm("cvt.rn.bf16x2.f32 %0, %1, %1;" : "=r"(w1) : "f"(wlo_f));  // {wlo, wlo}

    int ch  = bq >> 4;               // chunk within split
    int bkl = bq & 15;               // base-k within chunk
    uint32_t byte = swz((uint32_t)(n * 128 + 8 * bkl));   // 8B-aligned, swizzle-safe
    char* cb = (char*)(g_Bsw + (size_t)(s * CHUNKS + ch) * 1024);
    *(uint2*)(cb + byte) = make_uint2(w0, w1);
}

// ---------------------------------------------------------------------------
// Main: bf16 mma.sync split-GEMM with on-the-fly split products.
// grid = (32, SPLITK), 256 threads = 8 warps; warp w owns rows 16w..16w+15.
// ---------------------------------------------------------------------------
__global__ void __launch_bounds__(256) main_kernel(const float* __restrict__ x) {
    extern __shared__ char smem[];
    float (*xs)[33] = (float (*)[33])(smem + OFF_XS);
    int*   sIdx     = (int*)(smem + OFF_IDX);
    const uint32_t sA  = smem_u32(smem) + OFF_SA;
    const uint32_t sB0 = smem_u32(smem) + OFF_SB;

    const int t  = threadIdx.x;
    const int l  = t & 31, w = t >> 5;
    const int m0 = blockIdx.x * MT;
    const int s  = blockIdx.y;
    const int r  = t & 127;          // owned product row
    const int h  = t >> 7;           // base-k half of chunk

    // xs: row r, halves by h; sentinel col 32 = 1.0
    {
        const float4* xrow = (const float4*)(x + (size_t)(m0 + r) * F_DIM);
        #pragma unroll
        for (int i = 0; i < 4; i++) {
            float4 v = xrow[h * 4 + i];
            int c = (h * 4 + i) * 4;
            xs[r][c] = v.x; xs[r][c + 1] = v.y; xs[r][c + 2] = v.z; xs[r][c + 3] = v.w;
        }
        if (h == 0) xs[r][32] = 1.0f;
    }
    for (int i = t; i < BK_PAD; i += 256) sIdx[i] = g_packed[s * BK_PAD + i];

    // Prologue: B chunk 0 -> buffer 0
    {
        const uint4* src = g_Bsw + (size_t)(s * CHUNKS) * 1024;
        #pragma unroll
        for (int i = 0; i < 4; i++) {
            int f4 = t + 256 * i;
            cp_async16(sB0 + f4 * 16, src + f4);
        }
        asm volatile("cp.async.commit_group;\n");
    }

    float acc[16][4];
    #pragma unroll
    for (int i = 0; i < 16; i++)
        #pragma unroll
        for (int j = 0; j < 4; j++) acc[i][j] = 0.0f;

    // ldmatrix per-thread address components (mask constant: row%8 == l&7)
    const uint32_t mask   = (uint32_t)((l & 7) << 4);
    const uint32_t a_base = (uint32_t)((16 * w + (l & 15)) * 128 + ((l >> 4) << 4));
    const uint32_t b_base = (uint32_t)(((l & 7) + ((l >> 4) << 3)) * 128 + (((l >> 3) & 1) << 4));
    // product store bases: 4 uint4 per thread at bytes r*128 + 64h + 16*pp
    const uint32_t p_base = (uint32_t)(r * 128 + 64 * h);

    for (int c = 0; c < CHUNKS; c++) {
        __syncthreads();   // prev GEMM done reading sA and sB[(c+1)&1]

        // Products: 8 base-k for (row r, half h) -> sA swizzled bf16x2
        {
            const int cb = c * CH_BK + h * 8;
            #pragma unroll
            for (int pp = 0; pp < 4; pp++) {
                uint32_t wv[2];
                #pragma unroll
                for (int v = 0; v < 2; v++) {
                    int p = sIdx[cb + 2 * pp + v];
                    float pf = xs[r][p & 63] * xs[r][(p >> 6) & 63] * xs[r][(p >> 12) & 63];
                    float hi = __bfloat162float(__float2bfloat16(pf));
                    float lo = pf - hi;
                    // memory order [phi, plo]: lower half = phi
                    asm("cvt.rn.bf16x2.f32 %0, %1, %2;" : "=r"(wv[v]) : "f"(lo), "f"(pf));
                }
                uint32_t byte = swz(p_base + 16u * pp);
                asm volatile("st.shared.v4.b32 [%0], {%1,%2,%3,%4};"
                             :: "r"(sA + byte), "r"(wv[0]), "r"(wv[0]), "r"(wv[1]), "r"(wv[1])
                             : "memory");
            }
        }

        // Prefetch B chunk c+1 into other buffer
        if (c + 1 < CHUNKS) {
            const uint4* src = g_Bsw + (size_t)(s * CHUNKS + c + 1) * 1024;
            uint32_t dst = sB0 + ((c + 1) & 1) * 16384;
            #pragma unroll
            for (int i = 0; i < 4; i++) {
                int f4 = t + 256 * i;
                cp_async16(dst + f4 * 16, src + f4);
            }
        }
        asm volatile("cp.async.commit_group;\n");
        asm volatile("cp.async.wait_group 1;\n");   // chunk c's B landed
        __syncthreads();                            // products + B visible

        const uint32_t sBq = sB0 + (c & 1) * 16384;
        #pragma unroll
        for (int ks = 0; ks < 4; ks++) {
            uint32_t a0, a1, a2, a3;
            asm volatile("ldmatrix.sync.aligned.m8n8.x4.shared.b16 {%0,%1,%2,%3}, [%4];"
                         : "=r"(a0), "=r"(a1), "=r"(a2), "=r"(a3)
                         : "r"(sA + ((a_base + (ks << 5)) ^ mask)));
            #pragma unroll
            for (int j = 0; j < 8; j++) {
                uint32_t b0, b1, b2, b3;
                asm volatile("ldmatrix.sync.aligned.m8n8.x4.shared.b16 {%0,%1,%2,%3}, [%4];"
                             : "=r"(b0), "=r"(b1), "=r"(b2), "=r"(b3)
                             : "r"(sBq + ((b_base + j * 2048 + (ks << 5)) ^ mask)));
                asm volatile("mma.sync.aligned.m16n8k16.row.col.f32.bf16.bf16.f32 "
                             "{%0,%1,%2,%3}, {%4,%5,%6,%7}, {%8,%9}, {%0,%1,%2,%3};"
                             : "+f"(acc[2*j][0]), "+f"(acc[2*j][1]),
                               "+f"(acc[2*j][2]), "+f"(acc[2*j][3])
                             : "r"(a0), "r"(a1), "r"(a2), "r"(a3), "r"(b0), "r"(b1));
                asm volatile("mma.sync.aligned.m16n8k16.row.col.f32.bf16.bf16.f32 "
                             "{%0,%1,%2,%3}, {%4,%5,%6,%7}, {%8,%9}, {%0,%1,%2,%3};"
                             : "+f"(acc[2*j+1][0]), "+f"(acc[2*j+1][1]),
                               "+f"(acc[2*j+1][2]), "+f"(acc[2*j+1][3])
                             : "r"(a0), "r"(a1), "r"(a2), "r"(a3), "r"(b2), "r"(b3));
            }
        }
    }

    // Epilogue: D rows l>>2 / +8, cols 8nt + 2(l&3)
    {
        float* prow = g_partial + ((size_t)s * B_DIM + m0 + 16 * w + (l >> 2)) * C_DIM + 2 * (l & 3);
        #pragma unroll
        for (int nt = 0; nt < 16; nt++) {
            *(float2*)(prow + 8 * nt)               = make_float2(acc[nt][0], acc[nt][1]);
            *(float2*)(prow + 8 * C_DIM + 8 * nt)   = make_float2(acc[nt][2], acc[nt][3]);
        }
    }
}

// ---------------------------------------------------------------------------
// Reduce: out = bias + sum_s partial[s]
// ---------------------------------------------------------------------------
__global__ void reduce_kernel(const float* __restrict__ bias,
                              float* __restrict__ out) {
    int i = blockIdx.x * blockDim.x + threadIdx.x;
    if (i >= (B_DIM * C_DIM) / 4) return;
    float4 accv = ((const float4*)bias)[i & 31];
    const float4* p4 = (const float4*)g_partial;
    #pragma unroll
    for (int s = 0; s < SPLITK; s++) {
        float4 v = p4[(size_t)s * (B_DIM * C_DIM / 4) + i];
        accv.x += v.x; accv.y += v.y; accv.z += v.z; accv.w += v.w;
    }
    ((float4*)out)[i] = accv;
}

// ---------------------------------------------------------------------------
// Launch
// ---------------------------------------------------------------------------
extern "C" void kernel_launch(void* const* d_in, const int* in_sizes, int n_in,
                              void* d_out, int out_size) {
    const float* x    = (const float*)d_in[0];
    const float* bias = (const float*)d_in[1];
    const float* W1   = (const float*)d_in[2];
    const float* W2   = (const float*)d_in[3];
    const float* W3   = (const float*)d_in[4];
    const int*   idx1 = (const int*)d_in[5];
    const int*   idx2 = (const int*)d_in[6];
    const int*   idx3 = (const int*)d_in[7];
    float* out = (float*)d_out;

    cudaFuncSetAttribute(main_kernel, cudaFuncAttributeMaxDynamicSharedMemorySize, SMEM_BYTES);

    pack_kernel<<<(SPLITK * BK_PAD + 127) / 128, 128>>>(idx1, idx2, idx3);
    wq_kernel<<<(SPLITK * BK_PAD * C_DIM + 255) / 256, 256>>>(W1, W2, W3);

    dim3 grid(B_DIM / MT, SPLITK);   // (32, 4) = 128 blocks
    main_kernel<<<grid, 256, SMEM_BYTES>>>(x);

    reduce_kernel<<<(B_DIM * C_DIM / 4 + 255) / 256, 256>>>(bias, out);
}

// round 16
// speedup vs baseline: 1.7220x; 1.0585x over previous
#include <cuda_runtime.h>
#include <cuda_bf16.h>
#include <cstdint>

// Problem constants
#define B_DIM    4096
#define F_DIM    32
#define C_DIM    128
#define K_TOT    5488
#define SPLITK   4
#define BK_SPL   1372            // real base-k per split (4*1372 = 5488)
#define BK_PAD   1376            // padded: 86 chunks * 16
#define CH_BK    16              // base-k per chunk
#define CHUNKS   86
#define MT       128

// Scratch (static __device__ — no allocations allowed)
__device__ int   g_packed[SPLITK * BK_PAD];                       // sentinel=32
__device__ uint4 g_Bsw[SPLITK * CHUNKS * 1024];                   // pre-swizzled 16KB B chunks
__device__ float g_partial[(size_t)SPLITK * B_DIM * C_DIM];       // 8.4 MB

// Dynamic smem layout (bytes)
#define OFF_XS    0                       // 128*33*4 = 16896
#define OFF_IDX   16896                   // 1376*4   = 5504 -> pad
#define OFF_SA    22528                   // 2 x 16384 (double buffer)
#define OFF_SB    55296                   // 3 x 16384 (triple buffer ring)
#define SMEM_BYTES 104448

// swizzle within a 16KB tile of 128-byte rows: XOR 16B-chunk-col with row%8
__device__ __forceinline__ uint32_t swz(uint32_t b) { return b ^ ((b >> 3) & 0x70); }

__device__ __forceinline__ uint32_t smem_u32(const void* p) {
    uint32_t a;
    asm("{ .reg .u64 t; cvta.to.shared.u64 t, %1; cvt.u32.u64 %0, t; }" : "=r"(a) : "l"(p));
    return a;
}
__device__ __forceinline__ void cp_async16(uint32_t smem_dst, const void* gmem_src) {
    asm volatile("cp.async.cg.shared.global [%0], [%1], 16;\n" :: "r"(smem_dst), "l"(gmem_src));
}

// ---------------------------------------------------------------------------
// Prep 1: pack combo indices per split (sentinel 32 -> xs[.][32]=1)
// ---------------------------------------------------------------------------
__global__ void pack_kernel(const int* __restrict__ idx1,
                            const int* __restrict__ idx2,
                            const int* __restrict__ idx3) {
    int i = blockIdx.x * blockDim.x + threadIdx.x;
    if (i >= SPLITK * BK_PAD) return;
    int s = i / BK_PAD, bq = i - s * BK_PAD;
    int a = 32, b = 32, c = 32;
    if (bq < BK_SPL) {
        int k = s * BK_SPL + bq;
        if (k < 32) {
            a = idx1[k];
        } else if (k < 528) {
            int j = k - 32; a = idx2[2 * j]; b = idx2[2 * j + 1];
        } else {
            int j = k - 528; a = idx3[3 * j]; b = idx3[3 * j + 1]; c = idx3[3 * j + 2];
        }
    }
    g_packed[i] = a | (b << 6) | (c << 12);
}

// ---------------------------------------------------------------------------
// Prep 2: pre-swizzled bf16 B chunks, layout [n=128 rows][k'=64 cols bf16].
// Per base-k cols {4b..4b+3}: {whi, whi, wlo, wlo}.
// ---------------------------------------------------------------------------
__global__ void wq_kernel(const float* __restrict__ W1,
                          const float* __restrict__ W2,
                          const float* __restrict__ W3) {
    int e = blockIdx.x * blockDim.x + threadIdx.x;
    if (e >= SPLITK * BK_PAD * C_DIM) return;
    int n  = e & 127;
    int sb = e >> 7;
    int s  = sb / BK_PAD, bq = sb - s * BK_PAD;

    float w = 0.0f;
    if (bq < BK_SPL) {
        int k = s * BK_SPL + bq;
        if (k < 32)       w = W1[k * C_DIM + n];
        else if (k < 528) w = W2[(k - 32) * C_DIM + n];
        else              w = W3[(k - 528) * C_DIM + n];
    }
    float whi_f = __bfloat162float(__float2bfloat16(w));
    float wlo_f = w - whi_f;
    uint32_t w0, w1;
    asm("cvt.rn.bf16x2.f32 %0, %1, %1;" : "=r"(w0) : "f"(w));      // {whi, whi}
    asm("cvt.rn.bf16x2.f32 %0, %1, %1;" : "=r"(w1) : "f"(wlo_f));  // {wlo, wlo}

    int ch  = bq >> 4;               // chunk within split
    int bkl = bq & 15;               // base-k within chunk
    uint32_t byte = swz((uint32_t)(n * 128 + 8 * bkl));
    char* cb = (char*)(g_Bsw + (size_t)(s * CHUNKS + ch) * 1024);
    *(uint2*)(cb + byte) = make_uint2(w0, w1);
}

// ---------------------------------------------------------------------------
// Main: bf16 mma.sync split-GEMM, 4Mx2N warp tiling, 1 barrier/chunk.
// grid = (32, SPLITK), 256 threads = 8 warps.
// Warp (wm = w>>1) owns rows 32wm..32wm+31; (wn = w&1) owns cols 64wn..+63.
// ---------------------------------------------------------------------------
__global__ void __launch_bounds__(256) main_kernel(const float* __restrict__ x) {
    extern __shared__ char smem[];
    float (*xs)[33] = (float (*)[33])(smem + OFF_XS);
    int*   sIdx     = (int*)(smem + OFF_IDX);
    const uint32_t sA0 = smem_u32(smem) + OFF_SA;
    const uint32_t sB0 = smem_u32(smem) + OFF_SB;

    const int t  = threadIdx.x;
    const int l  = t & 31, w = t >> 5;
    const int wm = w >> 1, wn = w & 1;
    const int m0 = blockIdx.x * MT;
    const int s  = blockIdx.y;
    const int r  = t & 127;          // owned product row
    const int h  = t >> 7;           // base-k half of chunk

    // xs: row r, halves by h; sentinel col 32 = 1.0
    {
        const float4* xrow = (const float4*)(x + (size_t)(m0 + r) * F_DIM);
        #pragma unroll
        for (int i = 0; i < 4; i++) {
            float4 v = xrow[h * 4 + i];
            int c = (h * 4 + i) * 4;
            xs[r][c] = v.x; xs[r][c + 1] = v.y; xs[r][c + 2] = v.z; xs[r][c + 3] = v.w;
        }
        if (h == 0) xs[r][32] = 1.0f;
    }
    for (int i = t; i < BK_PAD; i += 256) sIdx[i] = g_packed[s * BK_PAD + i];

    // Prologue: B chunk 0 -> ring slot 0
    {
        const uint4* src = g_Bsw + (size_t)(s * CHUNKS) * 1024;
        #pragma unroll
        for (int i = 0; i < 4; i++) {
            int f4 = t + 256 * i;
            cp_async16(sB0 + f4 * 16, src + f4);
        }
        asm volatile("cp.async.commit_group;\n");
    }

    float acc[16][4];
    #pragma unroll
    for (int i = 0; i < 16; i++)
        #pragma unroll
        for (int j = 0; j < 4; j++) acc[i][j] = 0.0f;

    // ldmatrix per-thread address components (mask: XOR chunk-col with row%8)
    const uint32_t mask   = (uint32_t)((l & 7) << 4);
    const uint32_t a_base = (uint32_t)((32 * wm + (l & 15)) * 128 + ((l >> 4) << 4));
    const uint32_t b_base = (uint32_t)((64 * wn + (l & 7) + ((l >> 4) << 3)) * 128
                                       + (((l >> 3) & 1) << 4));
    const uint32_t p_base = (uint32_t)(r * 128 + 64 * h);

    int rs = 0;          // ring slot of chunk c (c mod 3)
    for (int c = 0; c < CHUNKS; c++) {
        // Products: 8 base-k for (row r, half h) -> sA[c&1] swizzled bf16x2
        {
            const uint32_t sAb = sA0 + (uint32_t)((c & 1) << 14);
            const int cb = c * CH_BK + h * 8;
            #pragma unroll
            for (int pp = 0; pp < 4; pp++) {
                uint32_t wv[2];
                #pragma unroll
                for (int v = 0; v < 2; v++) {
                    int p = sIdx[cb + 2 * pp + v];
                    float pf = xs[r][p & 63] * xs[r][(p >> 6) & 63] * xs[r][(p >> 12) & 63];
                    float hi = __bfloat162float(__float2bfloat16(pf));
                    float lo = pf - hi;
                    asm("cvt.rn.bf16x2.f32 %0, %1, %2;" : "=r"(wv[v]) : "f"(lo), "f"(pf));
                }
                uint32_t byte = swz(p_base + 16u * pp);
                asm volatile("st.shared.v4.b32 [%0], {%1,%2,%3,%4};"
                             :: "r"(sAb + byte), "r"(wv[0]), "r"(wv[0]), "r"(wv[1]), "r"(wv[1])
                             : "memory");
            }
        }

        // Prefetch B chunk c+1 into ring slot (c+1)%3
        if (c + 1 < CHUNKS) {
            const uint4* src = g_Bsw + (size_t)(s * CHUNKS + c + 1) * 1024;
            int ns = rs + 1; if (ns == 3) ns = 0;
            uint32_t dst = sB0 + (uint32_t)(ns << 14);
            #pragma unroll
            for (int i = 0; i < 4; i++) {
                int f4 = t + 256 * i;
                cp_async16(dst + f4 * 16, src + f4);
            }
        }
        asm volatile("cp.async.commit_group;\n");
        asm volatile("cp.async.wait_group 1;\n");   // chunk c's B landed
        __syncthreads();                            // products(c) + B(c) visible

        const uint32_t sAq = sA0 + (uint32_t)((c & 1) << 14);
        const uint32_t sBq = sB0 + (uint32_t)(rs << 14);
        #pragma unroll
        for (int ks = 0; ks < 4; ks++) {
            uint32_t A[2][4];
            #pragma unroll
            for (int mt = 0; mt < 2; mt++) {
                asm volatile("ldmatrix.sync.aligned.m8n8.x4.shared.b16 {%0,%1,%2,%3}, [%4];"
                             : "=r"(A[mt][0]), "=r"(A[mt][1]), "=r"(A[mt][2]), "=r"(A[mt][3])
                             : "r"(sAq + ((a_base + mt * 2048 + (ks << 5)) ^ mask)));
            }
            #pragma unroll
            for (int jn = 0; jn < 4; jn++) {
                uint32_t b0, b1, b2, b3;
                asm volatile("ldmatrix.sync.aligned.m8n8.x4.shared.b16 {%0,%1,%2,%3}, [%4];"
                             : "=r"(b0), "=r"(b1), "=r"(b2), "=r"(b3)
                             : "r"(sBq + ((b_base + jn * 2048 + (ks << 5)) ^ mask)));
                #pragma unroll
                for (int mt = 0; mt < 2; mt++) {
                    int ai = mt * 8 + 2 * jn;
                    asm volatile("mma.sync.aligned.m16n8k16.row.col.f32.bf16.bf16.f32 "
                                 "{%0,%1,%2,%3}, {%4,%5,%6,%7}, {%8,%9}, {%0,%1,%2,%3};"
                                 : "+f"(acc[ai][0]), "+f"(acc[ai][1]),
                                   "+f"(acc[ai][2]), "+f"(acc[ai][3])
                                 : "r"(A[mt][0]), "r"(A[mt][1]), "r"(A[mt][2]), "r"(A[mt][3]),
                                   "r"(b0), "r"(b1));
                    asm volatile("mma.sync.aligned.m16n8k16.row.col.f32.bf16.bf16.f32 "
                                 "{%0,%1,%2,%3}, {%4,%5,%6,%7}, {%8,%9}, {%0,%1,%2,%3};"
                                 : "+f"(acc[ai + 1][0]), "+f"(acc[ai + 1][1]),
                                   "+f"(acc[ai + 1][2]), "+f"(acc[ai + 1][3])
                                 : "r"(A[mt][0]), "r"(A[mt][1]), "r"(A[mt][2]), "r"(A[mt][3]),
                                   "r"(b2), "r"(b3));
                }
            }
        }
        rs = rs + 1; if (rs == 3) rs = 0;
    }

    // Epilogue: D rows 32wm+16mt+(l>>2)/+8, cols 64wn+16jn+8nb+2(l&3)
    #pragma unroll
    for (int mt = 0; mt < 2; mt++) {
        float* prow = g_partial
            + ((size_t)s * B_DIM + m0 + 32 * wm + 16 * mt + (l >> 2)) * C_DIM
            + 64 * wn + 2 * (l & 3);
        #pragma unroll
        for (int jn = 0; jn < 4; jn++)
            #pragma unroll
            for (int nb = 0; nb < 2; nb++) {
                int ai = mt * 8 + 2 * jn + nb;
                int col = 16 * jn + 8 * nb;
                *(float2*)(prow + col)             = make_float2(acc[ai][0], acc[ai][1]);
                *(float2*)(prow + 8 * C_DIM + col) = make_float2(acc[ai][2], acc[ai][3]);
            }
    }
}

// ---------------------------------------------------------------------------
// Reduce: out = bias + sum_s partial[s]
// ---------------------------------------------------------------------------
__global__ void reduce_kernel(const float* __restrict__ bias,
                              float* __restrict__ out) {
    int i = blockIdx.x * blockDim.x + threadIdx.x;
    if (i >= (B_DIM * C_DIM) / 4) return;
    float4 accv = ((const float4*)bias)[i & 31];
    const float4* p4 = (const float4*)g_partial;
    #pragma unroll
    for (int s = 0; s < SPLITK; s++) {
        float4 v = p4[(size_t)s * (B_DIM * C_DIM / 4) + i];
        accv.x += v.x; accv.y += v.y; accv.z += v.z; accv.w += v.w;
    }
    ((float4*)out)[i] = accv;
}

// ---------------------------------------------------------------------------
// Launch
// ---------------------------------------------------------------------------
extern "C" void kernel_launch(void* const* d_in, const int* in_sizes, int n_in,
                              void* d_out, int out_size) {
    const float* x    = (const float*)d_in[0];
    const float* bias = (const float*)d_in[1];
    const float* W1   = (const float*)d_in[2];
    const float* W2   = (const float*)d_in[3];
    const float* W3   = (const float*)d_in[4];
    const int*   idx1 = (const int*)d_in[5];
    const int*   idx2 = (const int*)d_in[6];
    const int*   idx3 = (const int*)d_in[7];
    float* out = (float*)d_out;

    cudaFuncSetAttribute(main_kernel, cudaFuncAttributeMaxDynamicSharedMemorySize, SMEM_BYTES);

    pack_kernel<<<(SPLITK * BK_PAD + 127) / 128, 128>>>(idx1, idx2, idx3);
    wq_kernel<<<(SPLITK * BK_PAD * C_DIM + 255) / 256, 256>>>(W1, W2, W3);

    dim3 grid(B_DIM / MT, SPLITK);   // (32, 4) = 128 blocks
    main_kernel<<<grid, 256, SMEM_BYTES>>>(x);

    reduce_kernel<<<(B_DIM * C_DIM / 4 + 255) / 256, 256>>>(bias, out);
}

// round 17
// speedup vs baseline: 2.0834x; 1.2099x over previous
#include <cuda_runtime.h>
#include <cuda_bf16.h>
#include <cstdint>

// Problem constants
#define B_DIM    4096
#define F_DIM    32
#define C_DIM    128
#define K_TOT    5488
#define SPLITK   4
#define BK_SPL   1372            // real base-k per split (4*1372 = 5488)
#define BK_PAD   1376            // padded: 86 chunks * 16
#define CH_BK    16              // base-k per chunk -> 32 k' (phi|plo) x (whi|wlo)
#define CHUNKS   86
#define MT       128

// Scratch (static __device__ — no allocations allowed)
__device__ int   g_packed[SPLITK * BK_PAD];                       // sentinel=32
__device__ uint4 g_Bsw[SPLITK * CHUNKS * 512];                    // pre-swizzled 8KB B chunks
__device__ float g_partial[(size_t)SPLITK * B_DIM * C_DIM];       // 8.4 MB

// Dynamic smem layout (bytes)
#define OFF_XS    0                       // 128*33*4 = 16896
#define OFF_IDX   16896                   // 1376*4   = 5504 -> pad to 22528
#define OFF_SA    22528                   // 2 x 8192 (double buffer)
#define OFF_SB    38912                   // 3 x 8192 (triple buffer ring)
#define SMEM_BYTES 63488

// SW64 swizzle for 64-byte-pitch tiles: XOR bits[5:4] with bits[8:7]
__device__ __host__ __forceinline__ uint32_t swz64(uint32_t b) { return b ^ ((b >> 3) & 0x30); }

__device__ __forceinline__ uint32_t smem_u32(const void* p) {
    uint32_t a;
    asm("{ .reg .u64 t; cvta.to.shared.u64 t, %1; cvt.u32.u64 %0, t; }" : "=r"(a) : "l"(p));
    return a;
}
__device__ __forceinline__ void cp_async16(uint32_t smem_dst, const void* gmem_src) {
    asm volatile("cp.async.cg.shared.global [%0], [%1], 16;\n" :: "r"(smem_dst), "l"(gmem_src));
}

// ---------------------------------------------------------------------------
// Prep 1: pack combo indices per split (sentinel 32 -> xs[.][32]=1)
// ---------------------------------------------------------------------------
__global__ void pack_kernel(const int* __restrict__ idx1,
                            const int* __restrict__ idx2,
                            const int* __restrict__ idx3) {
    int i = blockIdx.x * blockDim.x + threadIdx.x;
    if (i >= SPLITK * BK_PAD) return;
    int s = i / BK_PAD, bq = i - s * BK_PAD;
    int a = 32, b = 32, c = 32;
    if (bq < BK_SPL) {
        int k = s * BK_SPL + bq;
        if (k < 32) {
            a = idx1[k];
        } else if (k < 528) {
            int j = k - 32; a = idx2[2 * j]; b = idx2[2 * j + 1];
        } else {
            int j = k - 528; a = idx3[3 * j]; b = idx3[3 * j + 1]; c = idx3[3 * j + 2];
        }
    }
    g_packed[i] = a | (b << 6) | (c << 12);
}

// ---------------------------------------------------------------------------
// Prep 2: pre-swizzled bf16 B chunks, layout [n=128 rows][k'=32], pitch 64B.
// k' = bk      -> whi   (bytes 2bk)
// k' = 16 + bk -> wlo   (bytes 32 + 2bk)
// ---------------------------------------------------------------------------
__global__ void wq_kernel(const float* __restrict__ W1,
                          const float* __restrict__ W2,
                          const float* __restrict__ W3) {
    int e = blockIdx.x * blockDim.x + threadIdx.x;
    if (e >= SPLITK * BK_PAD * C_DIM) return;
    int n  = e & 127;
    int sb = e >> 7;
    int s  = sb / BK_PAD, bq = sb - s * BK_PAD;

    float w = 0.0f;
    if (bq < BK_SPL) {
        int k = s * BK_SPL + bq;
        if (k < 32)       w = W1[k * C_DIM + n];
        else if (k < 528) w = W2[(k - 32) * C_DIM + n];
        else              w = W3[(k - 528) * C_DIM + n];
    }
    __nv_bfloat16 whi = __float2bfloat16(w);
    float wlo_f = w - __bfloat162float(whi);
    __nv_bfloat16 wlo = __float2bfloat16(wlo_f);

    int ch  = bq >> 4;               // chunk within split
    int bkl = bq & 15;               // base-k within chunk
    char* cb = (char*)(g_Bsw + (size_t)(s * CHUNKS + ch) * 512);
    *(__nv_bfloat16*)(cb + swz64((uint32_t)(n * 64 + 2 * bkl)))      = whi;
    *(__nv_bfloat16*)(cb + swz64((uint32_t)(n * 64 + 32 + 2 * bkl))) = wlo;
}

// ---------------------------------------------------------------------------
// Main: bf16 mma.sync split-GEMM, 3-term precision split with fragment reuse.
// grid = (32, SPLITK), 256 threads = 8 warps, 4Mx2N warp tiling.
// Per chunk: A = [128m][phi(16) | plo(16)], B = [128n][whi(16) | wlo(16)],
// 3 k16-steps: AW*BW + AL*BW + AW*BL  (plo*wlo dropped, ~2^-16 rel).
// ---------------------------------------------------------------------------
__global__ void __launch_bounds__(256) main_kernel(const float* __restrict__ x) {
    extern __shared__ char smem[];
    float (*xs)[33] = (float (*)[33])(smem + OFF_XS);
    int*   sIdx     = (int*)(smem + OFF_IDX);
    const uint32_t sA0 = smem_u32(smem) + OFF_SA;
    const uint32_t sB0 = smem_u32(smem) + OFF_SB;

    const int t  = threadIdx.x;
    const int l  = t & 31, w = t >> 5;
    const int wm = w >> 1, wn = w & 1;
    const int m0 = blockIdx.x * MT;
    const int s  = blockIdx.y;
    const int r  = t & 127;          // owned product row
    const int h  = t >> 7;           // base-k half of chunk

    // xs: row r, halves by h; sentinel col 32 = 1.0
    {
        const float4* xrow = (const float4*)(x + (size_t)(m0 + r) * F_DIM);
        #pragma unroll
        for (int i = 0; i < 4; i++) {
            float4 v = xrow[h * 4 + i];
            int c = (h * 4 + i) * 4;
            xs[r][c] = v.x; xs[r][c + 1] = v.y; xs[r][c + 2] = v.z; xs[r][c + 3] = v.w;
        }
        if (h == 0) xs[r][32] = 1.0f;
    }
    for (int i = t; i < BK_PAD; i += 256) sIdx[i] = g_packed[s * BK_PAD + i];

    // Prologue: B chunk 0 -> ring slot 0 (8KB = 512 uint4, 2 per thread)
    {
        const uint4* src = g_Bsw + (size_t)(s * CHUNKS) * 512;
        #pragma unroll
        for (int i = 0; i < 2; i++) {
            int f4 = t + 256 * i;
            cp_async16(sB0 + f4 * 16, src + f4);
        }
        asm volatile("cp.async.commit_group;\n");
    }

    float acc[16][4];
    #pragma unroll
    for (int i = 0; i < 16; i++)
        #pragma unroll
        for (int j = 0; j < 4; j++) acc[i][j] = 0.0f;

    // Per-lane swizzled base addresses (loop-invariant; keys invariant to mt/jn)
    const int      m_ln  = 32 * wm + (l & 15);
    const uint32_t keyA  = (uint32_t)(((m_ln >> 1) & 3) << 4);
    const uint32_t c0a   = (uint32_t)((l >> 4) << 4);
    const uint32_t aW    = (uint32_t)(m_ln * 64) + (c0a ^ keyA);
    const uint32_t aL    = (uint32_t)(m_ln * 64) + ((c0a + 32) ^ keyA);

    const int      n_ln  = 64 * wn + (l & 7) + ((l >> 4) << 3);
    const uint32_t keyB  = (uint32_t)(((n_ln >> 1) & 3) << 4);
    const uint32_t c0b   = (uint32_t)(((l >> 3) & 1) << 4);
    const uint32_t bW    = (uint32_t)(n_ln * 64) + (c0b ^ keyB);
    const uint32_t bL    = (uint32_t)(n_ln * 64) + ((c0b + 32) ^ keyB);

    const uint32_t keyR  = (uint32_t)(((r >> 1) & 3) << 4);
    const uint32_t pW    = (uint32_t)(r * 64) + (((uint32_t)(16 * h)) ^ keyR);
    const uint32_t pL    = (uint32_t)(r * 64) + (((uint32_t)(32 + 16 * h)) ^ keyR);

    int rs = 0;          // ring slot of chunk c (c mod 3)
    for (int c = 0; c < CHUNKS; c++) {
        // Products: 8 base-k for (row r, half h) -> phi/plo packed STS.128
        {
            const uint32_t sAb = sA0 + (uint32_t)((c & 1) << 13);
            const int cb = c * CH_BK + h * 8;
            float pf[8], lo[8];
            #pragma unroll
            for (int j = 0; j < 8; j++) {
                int p = sIdx[cb + j];
                pf[j] = xs[r][p & 63] * xs[r][(p >> 6) & 63] * xs[r][(p >> 12) & 63];
                lo[j] = pf[j] - __bfloat162float(__float2bfloat16(pf[j]));
            }
            uint32_t wph[4], wpl[4];
            #pragma unroll
            for (int p2 = 0; p2 < 4; p2++) {
                // upper half = element 2p2+1, lower half = element 2p2 (k' order)
                asm("cvt.rn.bf16x2.f32 %0, %1, %2;" : "=r"(wph[p2]) : "f"(pf[2*p2+1]), "f"(pf[2*p2]));
                asm("cvt.rn.bf16x2.f32 %0, %1, %2;" : "=r"(wpl[p2]) : "f"(lo[2*p2+1]), "f"(lo[2*p2]));
            }
            asm volatile("st.shared.v4.b32 [%0], {%1,%2,%3,%4};"
                         :: "r"(sAb + pW), "r"(wph[0]), "r"(wph[1]), "r"(wph[2]), "r"(wph[3])
                         : "memory");
            asm volatile("st.shared.v4.b32 [%0], {%1,%2,%3,%4};"
                         :: "r"(sAb + pL), "r"(wpl[0]), "r"(wpl[1]), "r"(wpl[2]), "r"(wpl[3])
                         : "memory");
        }

        // Prefetch B chunk c+1 into ring slot (c+1)%3
        if (c + 1 < CHUNKS) {
            const uint4* src = g_Bsw + (size_t)(s * CHUNKS + c + 1) * 512;
            int ns = rs + 1; if (ns == 3) ns = 0;
            uint32_t dst = sB0 + (uint32_t)(ns << 13);
            #pragma unroll
            for (int i = 0; i < 2; i++) {
                int f4 = t + 256 * i;
                cp_async16(dst + f4 * 16, src + f4);
            }
        }
        asm volatile("cp.async.commit_group;\n");
        asm volatile("cp.async.wait_group 1;\n");   // chunk c's B landed
        __syncthreads();                            // products(c) + B(c) visible

        const uint32_t sAq = sA0 + (uint32_t)((c & 1) << 13);
        const uint32_t sBq = sB0 + (uint32_t)(rs << 13);

        // Load A fragments once per chunk: AW (phi), AL (plo)
        uint32_t AWr[2][4], ALr[2][4];
        #pragma unroll
        for (int mt = 0; mt < 2; mt++) {
            asm volatile("ldmatrix.sync.aligned.m8n8.x4.shared.b16 {%0,%1,%2,%3}, [%4];"
                         : "=r"(AWr[mt][0]), "=r"(AWr[mt][1]), "=r"(AWr[mt][2]), "=r"(AWr[mt][3])
                         : "r"(sAq + aW + mt * 1024));
            asm volatile("ldmatrix.sync.aligned.m8n8.x4.shared.b16 {%0,%1,%2,%3}, [%4];"
                         : "=r"(ALr[mt][0]), "=r"(ALr[mt][1]), "=r"(ALr[mt][2]), "=r"(ALr[mt][3])
                         : "r"(sAq + aL + mt * 1024));
        }

        #pragma unroll
        for (int jn = 0; jn < 4; jn++) {
            uint32_t w0, w1, w2, w3, u0, u1, u2, u3;
            asm volatile("ldmatrix.sync.aligned.m8n8.x4.shared.b16 {%0,%1,%2,%3}, [%4];"
                         : "=r"(w0), "=r"(w1), "=r"(w2), "=r"(w3)
                         : "r"(sBq + bW + jn * 1024));
            asm volatile("ldmatrix.sync.aligned.m8n8.x4.shared.b16 {%0,%1,%2,%3}, [%4];"
                         : "=r"(u0), "=r"(u1), "=r"(u2), "=r"(u3)
                         : "r"(sBq + bL + jn * 1024));
            #pragma unroll
            for (int mt = 0; mt < 2; mt++) {
                const int ai = mt * 8 + 2 * jn;
#define MMA_ACC(AI, A0, A1, A2, A3, B0, B1) \
    asm volatile("mma.sync.aligned.m16n8k16.row.col.f32.bf16.bf16.f32 " \
                 "{%0,%1,%2,%3}, {%4,%5,%6,%7}, {%8,%9}, {%0,%1,%2,%3};" \
                 : "+f"(acc[AI][0]), "+f"(acc[AI][1]), "+f"(acc[AI][2]), "+f"(acc[AI][3]) \
                 : "r"(A0), "r"(A1), "r"(A2), "r"(A3), "r"(B0), "r"(B1))
                // phi * whi
                MMA_ACC(ai,     AWr[mt][0], AWr[mt][1], AWr[mt][2], AWr[mt][3], w0, w1);
                MMA_ACC(ai + 1, AWr[mt][0], AWr[mt][1], AWr[mt][2], AWr[mt][3], w2, w3);
                // plo * whi
                MMA_ACC(ai,     ALr[mt][0], ALr[mt][1], ALr[mt][2], ALr[mt][3], w0, w1);
                MMA_ACC(ai + 1, ALr[mt][0], ALr[mt][1], ALr[mt][2], ALr[mt][3], w2, w3);
                // phi * wlo
                MMA_ACC(ai,     AWr[mt][0], AWr[mt][1], AWr[mt][2], AWr[mt][3], u0, u1);
                MMA_ACC(ai + 1, AWr[mt][0], AWr[mt][1], AWr[mt][2], AWr[mt][3], u2, u3);
#undef MMA_ACC
            }
        }
        rs = rs + 1; if (rs == 3) rs = 0;
    }

    // Epilogue: D rows 32wm+16mt+(l>>2)/+8, cols 64wn+16jn+8nb+2(l&3)
    #pragma unroll
    for (int mt = 0; mt < 2; mt++) {
        float* prow = g_partial
            + ((size_t)s * B_DIM + m0 + 32 * wm + 16 * mt + (l >> 2)) * C_DIM
            + 64 * wn + 2 * (l & 3);
        #pragma unroll
        for (int jn = 0; jn < 4; jn++)
            #pragma unroll
            for (int nb = 0; nb < 2; nb++) {
                int ai = mt * 8 + 2 * jn + nb;
                int col = 16 * jn + 8 * nb;
                *(float2*)(prow + col)             = make_float2(acc[ai][0], acc[ai][1]);
                *(float2*)(prow + 8 * C_DIM + col) = make_float2(acc[ai][2], acc[ai][3]);
            }
    }
}

// ---------------------------------------------------------------------------
// Reduce: out = bias + sum_s partial[s]
// ---------------------------------------------------------------------------
__global__ void reduce_kernel(const float* __restrict__ bias,
                              float* __restrict__ out) {
    int i = blockIdx.x * blockDim.x + threadIdx.x;
    if (i >= (B_DIM * C_DIM) / 4) return;
    float4 accv = ((const float4*)bias)[i & 31];
    const float4* p4 = (const float4*)g_partial;
    #pragma unroll
    for (int s = 0; s < SPLITK; s++) {
        float4 v = p4[(size_t)s * (B_DIM * C_DIM / 4) + i];
        accv.x += v.x; accv.y += v.y; accv.z += v.z; accv.w += v.w;
    }
    ((float4*)out)[i] = accv;
}

// ---------------------------------------------------------------------------
// Launch
// ---------------------------------------------------------------------------
extern "C" void kernel_launch(void* const* d_in, const int* in_sizes, int n_in,
                              void* d_out, int out_size) {
    const float* x    = (const float*)d_in[0];
    const float* bias = (const float*)d_in[1];
    const float* W1   = (const float*)d_in[2];
    const float* W2   = (const float*)d_in[3];
    const float* W3   = (const float*)d_in[4];
    const int*   idx1 = (const int*)d_in[5];
    const int*   idx2 = (const int*)d_in[6];
    const int*   idx3 = (const int*)d_in[7];
    float* out = (float*)d_out;

    cudaFuncSetAttribute(main_kernel, cudaFuncAttributeMaxDynamicSharedMemorySize, SMEM_BYTES);

    pack_kernel<<<(SPLITK * BK_PAD + 127) / 128, 128>>>(idx1, idx2, idx3);
    wq_kernel<<<(SPLITK * BK_PAD * C_DIM + 255) / 256, 256>>>(W1, W2, W3);

    dim3 grid(B_DIM / MT, SPLITK);   // (32, 4) = 128 blocks
    main_kernel<<<grid, 256, SMEM_BYTES>>>(x);

    reduce_kernel<<<(B_DIM * C_DIM / 4 + 255) / 256, 256>>>(bias, out);
}